// round 6
// baseline (speedup 1.0000x reference)
#include <cuda_runtime.h>
#include <math.h>

// ---------------- problem constants ----------------
#define BS      2
#define DMODEL  256
#define HH      28
#define NTOK    784          // 28*28
#define WWIN    7
#define MW      4            // windows per side
#define NW      16
#define WS      49
#define KTOP    8
#define NHEAD   8
#define DH      32
#define DFF     512

// dedup attention: 784 token keys + 16 mean keys = 800, padded to 832
#define NCH2    2
#define CH2     416          // keys per chunk
#define KT      32           // key tile

typedef unsigned long long ull;

// ---------------- f32x2 packed math helpers ----------------
__device__ __forceinline__ ull pack2(float a, float b) {
    ull r;
    asm("mov.b64 %0, {%1, %2};" : "=l"(r) : "f"(a), "f"(b));
    return r;
}
__device__ __forceinline__ void unpack2(ull p, float& a, float& b) {
    asm("mov.b64 {%0, %1}, %2;" : "=f"(a), "=f"(b) : "l"(p));
}
__device__ __forceinline__ void ffma2(ull& d, ull a, ull b) {
    asm("fma.rn.f32x2 %0, %1, %2, %0;" : "+l"(d) : "l"(a), "l"(b));
}

// ---------------- scratch (device globals; no allocs allowed) ----------------
__device__ float g_q   [BS*NTOK*DMODEL];
__device__ float g_k   [BS*NTOK*DMODEL];
__device__ float g_v   [BS*NTOK*DMODEL];
__device__ float g_qm  [BS*NW*DMODEL];
__device__ float g_km  [BS*NW*DMODEL];
__device__ float g_vm  [BS*NW*DMODEL];
__device__ float g_cnt [BS*NW];
__device__ float g_pl  [BS*NHEAD*NCH2*NTOK];
__device__ float g_pacc[BS*NHEAD*NCH2*NTOK*DH];
__device__ float g_msg [BS*NTOK*DMODEL];
__device__ float g_msg2[BS*NTOK*DMODEL];
__device__ float g_mesg[BS*NTOK*DFF];
__device__ float g_y1  [BS*NTOK*DFF];
__device__ float g_y2  [BS*NTOK*DFF];
__device__ float g_z   [BS*NTOK*DMODEL];

// ---------------- packed-FMA GEMM, 32x64 tile, 128 threads ----------------
// C[M,N] = act(A[M,K] @ B[N,K]^T + bias)
// ATRANS: A is x in (b, K, NTOK) layout (transposed read); M = NTOK per batch, row b from bz.
// A stored in smem as duplicated pairs (no pack MOVs in mainloop).
template<bool ATRANS, int ACT>
__device__ __forceinline__ void gemm4_body(const float* __restrict__ A, const float* __restrict__ B,
                                           const float* __restrict__ bias, float* __restrict__ C,
                                           int M, int N, int K, int by, int bx, int b) {
    __shared__ __align__(16) float As2[16][68];   // [kq][2m],[2m+1] duplicated
    __shared__ __align__(16) float Bs[16][68];
    int bm = by * 32, bn = bx * 64;
    int tid = threadIdx.x;          // 0..127
    int tr = tid >> 3;              // 0..15 -> rows tr*2, tr*2+1
    int tc = tid & 7;               // 0..7

    ull acc[2][4];
    #pragma unroll
    for (int i = 0; i < 2; i++)
        #pragma unroll
        for (int p = 0; p < 4; p++) acc[i][p] = 0ull;

    for (int k0 = 0; k0 < K; k0 += 16) {
        // ---- A tile -> As2 (duplicated) ----
        if (ATRANS) {
            // read x[(b*K + k0+kq)*NTOK + n], coalesced float4 along tokens
            int kq = tid >> 3, nq = tid & 7;     // 16 x 8
            int n = bm + nq * 4;
            float4 av = make_float4(0.f, 0.f, 0.f, 0.f);
            if (n + 3 < M) av = *(const float4*)&A[((size_t)b * K + k0 + kq) * NTOK + n];
            int m2 = 2 * (nq * 4);
            As2[kq][m2 + 0] = av.x; As2[kq][m2 + 1] = av.x;
            As2[kq][m2 + 2] = av.y; As2[kq][m2 + 3] = av.y;
            As2[kq][m2 + 4] = av.z; As2[kq][m2 + 5] = av.z;
            As2[kq][m2 + 6] = av.w; As2[kq][m2 + 7] = av.w;
        } else {
            // 32 rows x 4 float4 = 128 float4, one per thread
            int r = tid >> 2, kq4 = tid & 3;
            int ga = bm + r;
            float4 av = (ga < M) ? *(const float4*)&A[(size_t)ga * K + k0 + kq4 * 4]
                                 : make_float4(0.f, 0.f, 0.f, 0.f);
            As2[kq4 * 4 + 0][2 * r] = av.x; As2[kq4 * 4 + 0][2 * r + 1] = av.x;
            As2[kq4 * 4 + 1][2 * r] = av.y; As2[kq4 * 4 + 1][2 * r + 1] = av.y;
            As2[kq4 * 4 + 2][2 * r] = av.z; As2[kq4 * 4 + 2][2 * r + 1] = av.z;
            As2[kq4 * 4 + 3][2 * r] = av.w; As2[kq4 * 4 + 3][2 * r + 1] = av.w;
        }
        // ---- B tile: 64 rows x 4 float4 = 256 float4, two per thread ----
        #pragma unroll
        for (int i = 0; i < 2; i++) {
            int f = tid + i * 128;
            int r = f >> 2, kq4 = f & 3;
            int gb = bn + r;
            float4 bv = (gb < N) ? *(const float4*)&B[(size_t)gb * K + k0 + kq4 * 4]
                                 : make_float4(0.f, 0.f, 0.f, 0.f);
            Bs[kq4 * 4 + 0][r] = bv.x;
            Bs[kq4 * 4 + 1][r] = bv.y;
            Bs[kq4 * 4 + 2][r] = bv.z;
            Bs[kq4 * 4 + 3][r] = bv.w;
        }
        __syncthreads();
        #pragma unroll
        for (int kq = 0; kq < 16; kq++) {
            ull a0 = *(const ull*)&As2[kq][4 * tr];
            ull a1 = *(const ull*)&As2[kq][4 * tr + 2];
            ulonglong2 b0 = *(const ulonglong2*)&Bs[kq][tc * 4];
            ulonglong2 b1 = *(const ulonglong2*)&Bs[kq][32 + tc * 4];
            ffma2(acc[0][0], a0, b0.x); ffma2(acc[0][1], a0, b0.y);
            ffma2(acc[0][2], a0, b1.x); ffma2(acc[0][3], a0, b1.y);
            ffma2(acc[1][0], a1, b0.x); ffma2(acc[1][1], a1, b0.y);
            ffma2(acc[1][2], a1, b1.x); ffma2(acc[1][3], a1, b1.y);
        }
        __syncthreads();
    }

    // epilogue (N % 64 == 0 so only row guard needed)
    #pragma unroll
    for (int i = 0; i < 2; i++) {
        int r = bm + tr * 2 + i;
        if (r >= M) continue;
        size_t ro = ATRANS ? ((size_t)b * NTOK + r) : (size_t)r;
        #pragma unroll
        for (int half = 0; half < 2; half++) {
            int c0 = bn + half * 32 + tc * 4;
            float4 o;
            unpack2(acc[i][half * 2 + 0], o.x, o.y);
            unpack2(acc[i][half * 2 + 1], o.z, o.w);
            if (bias) {
                o.x += bias[c0 + 0]; o.y += bias[c0 + 1];
                o.z += bias[c0 + 2]; o.w += bias[c0 + 3];
            }
            if (ACT == 1) {
                o.x = fmaxf(o.x, 0.f); o.y = fmaxf(o.y, 0.f);
                o.z = fmaxf(o.z, 0.f); o.w = fmaxf(o.w, 0.f);
            }
            *(float4*)&C[ro * N + c0] = o;
        }
    }
}

template<int ACT>
__global__ __launch_bounds__(128) void k_gemm4(const float* __restrict__ A, const float* __restrict__ B,
                                               const float* __restrict__ bias, float* __restrict__ C,
                                               int M, int N, int K) {
    gemm4_body<false, ACT>(A, B, bias, C, M, N, K, blockIdx.y, blockIdx.x, 0);
}

// fused QKV reading x directly: grid (12, 25, 2)
__global__ __launch_bounds__(128) void k_qkv(const float* __restrict__ x,
                                             const float* __restrict__ Wq, const float* __restrict__ Wk,
                                             const float* __restrict__ Wv,
                                             float* __restrict__ q, float* __restrict__ k, float* __restrict__ v) {
    int sel = blockIdx.x >> 2;
    const float* B = (sel == 0) ? Wq : (sel == 1) ? Wk : Wv;
    float* C = (sel == 0) ? q : (sel == 1) ? k : v;
    gemm4_body<true, 0>(x, B, nullptr, C, NTOK, DMODEL, DMODEL, blockIdx.y, blockIdx.x & 3, blockIdx.z);
}

// ---------------- per-window means of q,k,v ----------------
__global__ void k_means(const float* __restrict__ q, const float* __restrict__ k,
                        const float* __restrict__ v,
                        float* __restrict__ qm, float* __restrict__ km, float* __restrict__ vm) {
    int b = blockIdx.x / NW, w = blockIdx.x % NW;
    int c = threadIdx.x;
    int wr = w / MW, wc = w % MW;
    float sq = 0.f, sk = 0.f, sv = 0.f;
    for (int p = 0; p < WS; p++) {
        int pr = p / WWIN, pc = p % WWIN;
        int n  = (wr * WWIN + pr) * HH + wc * WWIN + pc;
        int o  = (b * NTOK + n) * DMODEL + c;
        sq += q[o]; sk += k[o]; sv += v[o];
    }
    int o = (b * NW + w) * DMODEL + c;
    qm[o] = sq * (1.f / 49.f);
    km[o] = sk * (1.f / 49.f);
    vm[o] = sv * (1.f / 49.f);
}

// ---------------- sim = qm @ km^T (16x16), top-8 select + window multiplicities ----------------
__global__ void k_topk(const float* __restrict__ qm, const float* __restrict__ km,
                       float* __restrict__ cnt) {
    int b = blockIdx.x;
    __shared__ __align__(16) float4 qs4[NW][65];   // padded: 2-way max bank conflict
    __shared__ __align__(16) float4 ks4[NW][65];
    __shared__ float sim[NW][NW];
    __shared__ int scnt[NW];
    int t = threadIdx.x;           // 256
    const float4* qm4 = (const float4*)qm;
    const float4* km4 = (const float4*)km;
    #pragma unroll
    for (int i = 0; i < 4; i++) {
        int idx = t + i * 256;     // 0..1023
        int row = idx >> 6, c = idx & 63;
        qs4[row][c] = qm4[(b * NW + row) * 64 + c];
        ks4[row][c] = km4[(b * NW + row) * 64 + c];
    }
    if (t < NW) scnt[t] = 0;
    __syncthreads();
    int i = t >> 4, j = t & 15;
    float4 s4 = make_float4(0.f, 0.f, 0.f, 0.f);
    #pragma unroll 8
    for (int c = 0; c < 64; c++) {
        float4 q4 = qs4[i][c], k4 = ks4[j][c];
        s4.x += q4.x * k4.x; s4.y += q4.y * k4.y;
        s4.z += q4.z * k4.z; s4.w += q4.w * k4.w;
    }
    sim[i][j] = (s4.x + s4.y) + (s4.z + s4.w);
    __syncthreads();
    if (t < NW) {
        float row[NW];
        #pragma unroll
        for (int j2 = 0; j2 < NW; j2++) row[j2] = sim[t][j2];
        #pragma unroll
        for (int r = 0; r < KTOP; r++) {
            int best = 0; float bv = -1e30f;
            #pragma unroll
            for (int j2 = 0; j2 < NW; j2++)
                if (row[j2] > bv) { bv = row[j2]; best = j2; }
            row[best] = -2e30f;
            atomicAdd(&scnt[best], 1);
        }
    }
    __syncthreads();
    if (t < NW) cnt[b * NW + t] = (float)scnt[t];
}

// ---------------- dedup attention over 800 unique keys (padded to 832) ----------------
__global__ __launch_bounds__(128) void k_attn(const float* __restrict__ qb,
                                              const float* __restrict__ kb,
                                              const float* __restrict__ vb,
                                              const float* __restrict__ km,
                                              const float* __restrict__ vm,
                                              const float* __restrict__ cnt,
                                              float* __restrict__ pl,
                                              float* __restrict__ pacc) {
    int qt0   = blockIdx.x * 128;
    int h     = blockIdx.y;
    int b     = blockIdx.z / NCH2;
    int chunk = blockIdx.z % NCH2;
    int t = threadIdx.x;
    int l = qt0 + t;
    int lq = (l < NTOK) ? l : 0;
    int w = lq / WS, p = lq % WS;
    int n = ((w / MW) * WWIN + p / WWIN) * HH + (w % MW) * WWIN + (p % WWIN);

    const ulonglong2* qrow = (const ulonglong2*)(qb + ((size_t)(b * NTOK + n) * DMODEL + h * DH));
    ull qp[16];
    #pragma unroll
    for (int i = 0; i < 8; i++) {
        ulonglong2 qq = qrow[i];
        qp[2 * i + 0] = qq.x;
        qp[2 * i + 1] = qq.y;
    }

    __shared__ __align__(16) float4 Ks[KT][DH / 4];
    __shared__ __align__(16) float4 Vs[KT][DH / 4];
    __shared__ float  wgt[KT];
    __shared__ float  scnt[NW];
    if (t < NW) scnt[t] = cnt[b * NW + t];

    float lsum = 0.f;
    ull acc[16];
    #pragma unroll
    for (int d = 0; d < 16; d++) acc[d] = 0ull;
    const float scale = 0.17677669529663687f;   // 32^-0.5

    int s0 = chunk * CH2;
    for (int tile = 0; tile < CH2 / KT; tile++) {
        int sbase = s0 + tile * KT;
        __syncthreads();
        #pragma unroll
        for (int i = 0; i < 4; i++) {
            int f = i * 128 + t;
            int r = f >> 3, c4 = f & 7;
            int rr = (r < KT) ? r : r - KT;
            int gr = sbase + rr;
            const float4* src;
            int rowbase;
            if (gr < NTOK) {
                src = (r < KT) ? (const float4*)kb : (const float4*)vb;
                rowbase = b * NTOK + gr;
            } else {
                int mi = gr - NTOK;
                if (mi >= NW) mi = 0;            // pad rows: weight 0, data harmless
                src = (r < KT) ? (const float4*)km : (const float4*)vm;
                rowbase = b * NW + mi;
            }
            float4 val = src[rowbase * (DMODEL / 4) + h * (DH / 4) + c4];
            if (r < KT) Ks[r][c4] = val; else Vs[r - KT][c4] = val;
        }
        if (t < KT) {
            int gr = sbase + t;
            float wv;
            if (gr < NTOK) {
                int win = (gr / (WWIN * HH)) * MW + (gr % HH) / WWIN;
                wv = scnt[win];
            } else wv = (gr < NTOK + NW) ? 16.f : 0.f;
            wgt[t] = wv;
        }
        __syncthreads();
        #pragma unroll 4
        for (int kk = 0; kk < KT; kk++) {
            float cw = wgt[kk];
            if (cw == 0.f) continue;             // uniform across block
            const ulonglong2* krow = (const ulonglong2*)&Ks[kk][0];
            ull s2 = 0ull;
            #pragma unroll
            for (int c = 0; c < 8; c++) {
                ulonglong2 kv = krow[c];
                ffma2(s2, qp[2 * c + 0], kv.x);
                ffma2(s2, qp[2 * c + 1], kv.y);
            }
            float slo, shi;
            unpack2(s2, slo, shi);
            float pe = cw * __expf((slo + shi) * scale);
            lsum += pe;
            ull pp = pack2(pe, pe);
            const ulonglong2* vrow = (const ulonglong2*)&Vs[kk][0];
            #pragma unroll
            for (int c = 0; c < 8; c++) {
                ulonglong2 vv = vrow[c];
                ffma2(acc[2 * c + 0], pp, vv.x);
                ffma2(acc[2 * c + 1], pp, vv.y);
            }
        }
    }
    if (l < NTOK) {
        int pbase = ((b * NHEAD + h) * NCH2 + chunk) * NTOK + l;
        pl[pbase] = lsum;
        #pragma unroll
        for (int d = 0; d < 16; d++) {
            float f0, f1;
            unpack2(acc[d], f0, f1);
            pacc[(size_t)pbase * DH + 2 * d + 0] = f0;
            pacc[(size_t)pbase * DH + 2 * d + 1] = f1;
        }
    }
}

// ---------------- combine split-K partials -> msg ----------------
__global__ void k_combine(const float* __restrict__ pl, const float* __restrict__ pacc,
                          float* __restrict__ msg) {
    int gq   = blockIdx.x * 8 + (threadIdx.x >> 5);   // BS*NHEAD*NTOK units
    int lane = threadIdx.x & 31;
    int b = gq / (NHEAD * NTOK);
    int rem = gq % (NHEAD * NTOK);
    int h = rem / NTOK, l = rem % NTOK;
    float Ls = 0.f, o = 0.f;
    #pragma unroll
    for (int c = 0; c < NCH2; c++) {
        int pbase = ((b * NHEAD + h) * NCH2 + c) * NTOK + l;
        Ls += pl[pbase];
        o  += pacc[(size_t)pbase * DH + lane];
    }
    msg[(b * NTOK + l) * DMODEL + h * DH + lane] = o / Ls;
}

// ---------------- LN1 + concat: message = [x^T | LN(msg2)] ----------------
__global__ void k_ln1(const float* __restrict__ msg2, const float* __restrict__ x,
                      const float* __restrict__ g, const float* __restrict__ bta,
                      float* __restrict__ message) {
    int row = blockIdx.x;       // 0..BS*NTOK-1
    int c = threadIdx.x;        // 256
    __shared__ float red[DMODEL];
    float v = msg2[row * DMODEL + c];
    red[c] = v; __syncthreads();
    for (int s = 128; s > 0; s >>= 1) { if (c < s) red[c] += red[c + s]; __syncthreads(); }
    float mu = red[0] * (1.f / DMODEL);
    __syncthreads();
    float dv = v - mu;
    red[c] = dv * dv; __syncthreads();
    for (int s = 128; s > 0; s >>= 1) { if (c < s) red[c] += red[c + s]; __syncthreads(); }
    float var = red[0] * (1.f / DMODEL);
    float outv = dv * rsqrtf(var + 1e-5f) * g[c] + bta[c];
    int b = row / NTOK, n = row % NTOK;
    message[row * DFF + DMODEL + c] = outv;
    message[row * DFF + c] = x[(b * DMODEL + c) * NTOK + n];
}

// ---------------- depthwise 3x3 conv + bias + exact gelu ----------------
__global__ void k_dwconv(const float* __restrict__ y1, const float* __restrict__ dww,
                         const float* __restrict__ dwb, float* __restrict__ y2) {
    int b = blockIdx.y;
    int nn = blockIdx.x;        // 0..783
    int c = threadIdx.x;        // 512
    int r = nn / HH, col = nn % HH;
    float s = 0.f;
    #pragma unroll
    for (int dr = -1; dr <= 1; dr++)
        #pragma unroll
        for (int dc = -1; dc <= 1; dc++) {
            int rr = r + dr, cc = col + dc;
            if (rr >= 0 && rr < HH && cc >= 0 && cc < HH)
                s += y1[(b * NTOK + rr * HH + cc) * DFF + c] * dww[c * 9 + (dr + 1) * 3 + (dc + 1)];
        }
    s += dwb[c];
    float gl = 0.5f * s * (1.f + erff(s * 0.70710678118654752f));
    y2[(b * NTOK + nn) * DFF + c] = gl;
}

// ---------------- LN2 + residual + coalesced transposed store ----------------
// grid (25, 2), block 256 (8 warps x 4 rows = 32 tokens per block)
__global__ __launch_bounds__(256) void k_ln2(const float* __restrict__ z, const float* __restrict__ x,
                                             const float* __restrict__ g, const float* __restrict__ bta,
                                             float* __restrict__ out) {
    __shared__ float tile[DMODEL][33];
    int b = blockIdx.y, n0 = blockIdx.x * 32;
    int rows = NTOK - n0; if (rows > 32) rows = 32;
    int wid = threadIdx.x >> 5, lane = threadIdx.x & 31;

    #pragma unroll
    for (int i = 0; i < 4; i++) {
        int rl = wid * 4 + i;
        if (rl >= rows) break;
        int row = b * NTOK + n0 + rl;
        float vals[8];
        float s = 0.f;
        #pragma unroll
        for (int j = 0; j < 8; j++) {
            vals[j] = z[(size_t)row * DMODEL + lane + j * 32];
            s += vals[j];
        }
        #pragma unroll
        for (int o = 16; o > 0; o >>= 1) s += __shfl_xor_sync(0xffffffff, s, o);
        float mu = s * (1.f / DMODEL);
        float sq = 0.f;
        #pragma unroll
        for (int j = 0; j < 8; j++) { float d = vals[j] - mu; sq += d * d; }
        #pragma unroll
        for (int o = 16; o > 0; o >>= 1) sq += __shfl_xor_sync(0xffffffff, sq, o);
        float rs = rsqrtf(sq * (1.f / DMODEL) + 1e-5f);
        #pragma unroll
        for (int j = 0; j < 8; j++) {
            int c = lane + j * 32;
            float o2 = (vals[j] - mu) * rs * g[c] + bta[c]
                     + x[((size_t)b * DMODEL + c) * NTOK + n0 + rl];
            tile[c][rl] = o2;
        }
    }
    __syncthreads();
    // coalesced store: warp w covers c = w*32..w*32+31; lane = token within tile
    if (lane < rows) {
        #pragma unroll
        for (int i = 0; i < 32; i++) {
            int c = wid * 32 + i;
            out[((size_t)b * DMODEL + c) * NTOK + n0 + lane] = tile[c][lane];
        }
    }
}

// ---------------- host launcher ----------------
static float* symf(const void* s) { void* p = nullptr; cudaGetSymbolAddress(&p, s); return (float*)p; }

extern "C" void kernel_launch(void* const* d_in, const int* in_sizes, int n_in,
                              void* d_out, int out_size) {
    const float* x    = (const float*)d_in[0];
    const float* Wq   = (const float*)d_in[1];
    const float* Wk   = (const float*)d_in[2];
    const float* Wv   = (const float*)d_in[3];
    const float* Wm   = (const float*)d_in[4];
    const float* ln1g = (const float*)d_in[5];
    const float* ln1b = (const float*)d_in[6];
    const float* fc1w = (const float*)d_in[7];
    const float* fc1b = (const float*)d_in[8];
    const float* dww  = (const float*)d_in[9];
    const float* dwb  = (const float*)d_in[10];
    const float* fc2w = (const float*)d_in[11];
    const float* fc2b = (const float*)d_in[12];
    const float* ln2g = (const float*)d_in[13];
    const float* ln2b = (const float*)d_in[14];
    float* out = (float*)d_out;

    float* q    = symf(g_q);
    float* k    = symf(g_k);
    float* v    = symf(g_v);
    float* qm   = symf(g_qm);
    float* km   = symf(g_km);
    float* vm   = symf(g_vm);
    float* cnt  = symf(g_cnt);
    float* pl   = symf(g_pl);
    float* pacc = symf(g_pacc);
    float* msg  = symf(g_msg);
    float* msg2 = symf(g_msg2);
    float* mesg = symf(g_mesg);
    float* y1   = symf(g_y1);
    float* y2   = symf(g_y2);
    float* z    = symf(g_z);

    const int M = BS * NTOK;   // 1568

    k_qkv<<<dim3(12, 25, BS), 128>>>(x, Wq, Wk, Wv, q, k, v);

    k_means<<<BS * NW, DMODEL>>>(q, k, v, qm, km, vm);
    k_topk<<<BS, 256>>>(qm, km, cnt);

    k_attn<<<dim3(7, NHEAD, BS * NCH2), 128>>>(q, k, v, km, vm, cnt, pl, pacc);
    k_combine<<<(BS * NHEAD * NTOK) / 8, 256>>>(pl, pacc, msg);

    k_gemm4<0><<<dim3(4, 49), 128>>>(msg, Wm, nullptr, msg2, M, DMODEL, DMODEL);
    k_ln1<<<M, DMODEL>>>(msg2, x, ln1g, ln1b, mesg);

    k_gemm4<1><<<dim3(8, 49), 128>>>(mesg, fc1w, fc1b, y1, M, DFF, DFF);
    k_dwconv<<<dim3(NTOK, BS), DFF>>>(y1, dww, dwb, y2);
    k_gemm4<0><<<dim3(4, 49), 128>>>(y2, fc2w, fc2b, z, M, DMODEL, DFF);

    k_ln2<<<dim3(25, BS), 256>>>(z, x, ln2g, ln2b, out);
}

// round 9
// speedup vs baseline: 1.2270x; 1.2270x over previous
#include <cuda_runtime.h>
#include <math.h>

// ---------------- problem constants ----------------
#define BS      2
#define DMODEL  256
#define HH      28
#define NTOK    784          // 28*28
#define WWIN    7
#define MW      4            // windows per side
#define NW      16
#define WS      49
#define KTOP    8
#define NHEAD   8
#define DH      32
#define DFF     512

// dedup attention: 784 token keys + 16 mean keys = 800, padded to 832
#define NCH2    4
#define CH2     208          // keys per chunk
#define KT      16           // key tile

typedef unsigned long long ull;

// ---------------- f32x2 packed math helpers ----------------
__device__ __forceinline__ ull pack2(float a, float b) {
    ull r;
    asm("mov.b64 %0, {%1, %2};" : "=l"(r) : "f"(a), "f"(b));
    return r;
}
__device__ __forceinline__ void unpack2(ull p, float& a, float& b) {
    asm("mov.b64 {%0, %1}, %2;" : "=f"(a), "=f"(b) : "l"(p));
}
__device__ __forceinline__ void ffma2(ull& d, ull a, ull b) {
    asm("fma.rn.f32x2 %0, %1, %2, %0;" : "+l"(d) : "l"(a), "l"(b));
}
__device__ __forceinline__ void add2(ull& d, ull a) {
    asm("add.rn.f32x2 %0, %0, %1;" : "+l"(d) : "l"(a));
}

// ---------------- scratch (device globals; no allocs allowed) ----------------
__device__ float g_xf  [BS*NTOK*DMODEL];
__device__ float g_q   [BS*NTOK*DMODEL];
__device__ float g_k   [BS*NTOK*DMODEL];
__device__ float g_v   [BS*NTOK*DMODEL];
__device__ float g_qm  [BS*NW*DMODEL];
__device__ float g_km  [BS*NW*DMODEL];
__device__ float g_vm  [BS*NW*DMODEL];
__device__ float g_cnt [BS*NW];
__device__ float g_pl  [BS*NHEAD*NCH2*NTOK];
__device__ float g_pacc[BS*NHEAD*NCH2*NTOK*DH];
__device__ float g_msg [BS*NTOK*DMODEL];
__device__ float g_msg2[BS*NTOK*DMODEL];
__device__ float g_mesg[BS*NTOK*DFF];
__device__ float g_y1  [BS*NTOK*DFF];
__device__ float g_y2  [BS*NTOK*DFF];
__device__ float g_z   [BS*NTOK*DMODEL];

// ---------------- x (b,d,hw) -> xf (b,hw,d) ----------------
__global__ void k_transpose(const float* __restrict__ x, float* __restrict__ xf) {
    __shared__ float tile[32][33];
    int b  = blockIdx.z;
    int c0 = blockIdx.y * 32, n0 = blockIdx.x * 32;
    int tx = threadIdx.x, ty = threadIdx.y;   // (32, 8)
    #pragma unroll
    for (int i = 0; i < 32; i += 8) {
        int c = c0 + ty + i, n = n0 + tx;
        if (c < DMODEL && n < NTOK) tile[ty + i][tx] = x[(b * DMODEL + c) * NTOK + n];
    }
    __syncthreads();
    #pragma unroll
    for (int i = 0; i < 32; i += 8) {
        int n = n0 + ty + i, c = c0 + tx;
        if (n < NTOK && c < DMODEL) xf[(b * NTOK + n) * DMODEL + c] = tile[tx][ty + i];
    }
}

// ---------------- packed-FMA GEMM: C[M,N] = act(A[M,K] @ B[N,K]^T + bias) ----------------
// 64x64 tile, 128 threads. Each thread: 4 rows x 8 cols as 16 packed f32x2.
__device__ __forceinline__ void gemm3_body(const float* __restrict__ A, const float* __restrict__ B,
                                           const float* __restrict__ bias, float* __restrict__ C,
                                           int M, int N, int K, int act, int by, int bx) {
    __shared__ __align__(16) float As[16][72];
    __shared__ __align__(16) float Bs[16][72];
    int bm = by * 64, bn = bx * 64;
    int tid = threadIdx.x;          // 0..127
    int tr = tid >> 3;              // 0..15
    int tc = tid & 7;               // 0..7

    ull acc[4][4];
    #pragma unroll
    for (int i = 0; i < 4; i++)
        #pragma unroll
        for (int p = 0; p < 4; p++) acc[i][p] = 0ull;

    for (int k0 = 0; k0 < K; k0 += 16) {
        #pragma unroll
        for (int i = 0; i < 2; i++) {
            int f = tid + i * 128;          // 0..255
            int r = f >> 2, kq4 = f & 3;
            int ga = bm + r;
            float4 av = (ga < M) ? *(const float4*)&A[(size_t)ga * K + k0 + kq4 * 4]
                                 : make_float4(0.f, 0.f, 0.f, 0.f);
            As[kq4 * 4 + 0][r] = av.x;
            As[kq4 * 4 + 1][r] = av.y;
            As[kq4 * 4 + 2][r] = av.z;
            As[kq4 * 4 + 3][r] = av.w;
            int gb = bn + r;
            float4 bv = (gb < N) ? *(const float4*)&B[(size_t)gb * K + k0 + kq4 * 4]
                                 : make_float4(0.f, 0.f, 0.f, 0.f);
            Bs[kq4 * 4 + 0][r] = bv.x;
            Bs[kq4 * 4 + 1][r] = bv.y;
            Bs[kq4 * 4 + 2][r] = bv.z;
            Bs[kq4 * 4 + 3][r] = bv.w;
        }
        __syncthreads();
        #pragma unroll
        for (int kq = 0; kq < 16; kq++) {
            float4 a4 = *(const float4*)&As[kq][tr * 4];
            ulonglong2 b0 = *(const ulonglong2*)&Bs[kq][tc * 4];
            ulonglong2 b1 = *(const ulonglong2*)&Bs[kq][32 + tc * 4];
            ull pa0 = pack2(a4.x, a4.x);
            ull pa1 = pack2(a4.y, a4.y);
            ull pa2 = pack2(a4.z, a4.z);
            ull pa3 = pack2(a4.w, a4.w);
            ffma2(acc[0][0], pa0, b0.x); ffma2(acc[0][1], pa0, b0.y);
            ffma2(acc[0][2], pa0, b1.x); ffma2(acc[0][3], pa0, b1.y);
            ffma2(acc[1][0], pa1, b0.x); ffma2(acc[1][1], pa1, b0.y);
            ffma2(acc[1][2], pa1, b1.x); ffma2(acc[1][3], pa1, b1.y);
            ffma2(acc[2][0], pa2, b0.x); ffma2(acc[2][1], pa2, b0.y);
            ffma2(acc[2][2], pa2, b1.x); ffma2(acc[2][3], pa2, b1.y);
            ffma2(acc[3][0], pa3, b0.x); ffma2(acc[3][1], pa3, b0.y);
            ffma2(acc[3][2], pa3, b1.x); ffma2(acc[3][3], pa3, b1.y);
        }
        __syncthreads();
    }

    #pragma unroll
    for (int i = 0; i < 4; i++) {
        int r = bm + tr * 4 + i;
        if (r >= M) continue;
        #pragma unroll
        for (int half = 0; half < 2; half++) {
            int c0 = bn + half * 32 + tc * 4;
            float4 o;
            unpack2(acc[i][half * 2 + 0], o.x, o.y);
            unpack2(acc[i][half * 2 + 1], o.z, o.w);
            if (bias) {
                o.x += bias[c0 + 0]; o.y += bias[c0 + 1];
                o.z += bias[c0 + 2]; o.w += bias[c0 + 3];
            }
            if (act == 1) {
                o.x = fmaxf(o.x, 0.f); o.y = fmaxf(o.y, 0.f);
                o.z = fmaxf(o.z, 0.f); o.w = fmaxf(o.w, 0.f);
            }
            *(float4*)&C[(size_t)r * N + c0] = o;
        }
    }
}

__global__ __launch_bounds__(128) void k_gemm3(const float* __restrict__ A, const float* __restrict__ B,
                                               const float* __restrict__ bias, float* __restrict__ C,
                                               int M, int N, int K, int act) {
    gemm3_body(A, B, bias, C, M, N, K, act, blockIdx.y, blockIdx.x);
}

// fused QKV: grid.x = 12 (3 weights x 4 col tiles), grid.y = 25
__global__ __launch_bounds__(128) void k_qkv(const float* __restrict__ A,
                                             const float* __restrict__ Wq, const float* __restrict__ Wk,
                                             const float* __restrict__ Wv,
                                             float* __restrict__ q, float* __restrict__ k, float* __restrict__ v) {
    int sel = blockIdx.x >> 2;
    const float* B = (sel == 0) ? Wq : (sel == 1) ? Wk : Wv;
    float* C = (sel == 0) ? q : (sel == 1) ? k : v;
    gemm3_body(A, B, nullptr, C, BS * NTOK, DMODEL, DMODEL, 0, blockIdx.y, blockIdx.x & 3);
}

// ---------------- per-window means of q,k,v ----------------
__global__ void k_means(const float* __restrict__ q, const float* __restrict__ k,
                        const float* __restrict__ v,
                        float* __restrict__ qm, float* __restrict__ km, float* __restrict__ vm) {
    int b = blockIdx.x / NW, w = blockIdx.x % NW;
    int c = threadIdx.x;
    int wr = w / MW, wc = w % MW;
    float sq = 0.f, sk = 0.f, sv = 0.f;
    for (int p = 0; p < WS; p++) {
        int pr = p / WWIN, pc = p % WWIN;
        int n  = (wr * WWIN + pr) * HH + wc * WWIN + pc;
        int o  = (b * NTOK + n) * DMODEL + c;
        sq += q[o]; sk += k[o]; sv += v[o];
    }
    int o = (b * NW + w) * DMODEL + c;
    qm[o] = sq * (1.f / 49.f);
    km[o] = sk * (1.f / 49.f);
    vm[o] = sv * (1.f / 49.f);
}

// ---------------- sim = qm @ km^T (16x16), top-8 select + window multiplicities ----------------
__global__ void k_topk(const float* __restrict__ qm, const float* __restrict__ km,
                       float* __restrict__ cnt) {
    int b = blockIdx.x;
    __shared__ __align__(16) float4 qs4[NW][65];   // padded: conflict-light
    __shared__ __align__(16) float4 ks4[NW][65];
    __shared__ float sim[NW][NW];
    __shared__ int scnt[NW];
    int t = threadIdx.x;           // 256
    const float4* qm4 = (const float4*)qm;
    const float4* km4 = (const float4*)km;
    #pragma unroll
    for (int i = 0; i < 4; i++) {
        int idx = t + i * 256;     // 0..1023
        int row = idx >> 6, c = idx & 63;
        qs4[row][c] = qm4[(b * NW + row) * 64 + c];
        ks4[row][c] = km4[(b * NW + row) * 64 + c];
    }
    if (t < NW) scnt[t] = 0;
    __syncthreads();
    int i = t >> 4, j = t & 15;
    float4 s4 = make_float4(0.f, 0.f, 0.f, 0.f);
    #pragma unroll 8
    for (int c = 0; c < 64; c++) {
        float4 q4 = qs4[i][c], k4 = ks4[j][c];
        s4.x += q4.x * k4.x; s4.y += q4.y * k4.y;
        s4.z += q4.z * k4.z; s4.w += q4.w * k4.w;
    }
    sim[i][j] = (s4.x + s4.y) + (s4.z + s4.w);
    __syncthreads();
    if (t < NW) {
        float row[NW];
        #pragma unroll
        for (int j2 = 0; j2 < NW; j2++) row[j2] = sim[t][j2];
        #pragma unroll
        for (int r = 0; r < KTOP; r++) {
            int best = 0; float bv = -1e30f;
            #pragma unroll
            for (int j2 = 0; j2 < NW; j2++)
                if (row[j2] > bv) { bv = row[j2]; best = j2; }
            row[best] = -2e30f;
            atomicAdd(&scnt[best], 1);
        }
    }
    __syncthreads();
    if (t < NW) cnt[b * NW + t] = (float)scnt[t];
}

// ---------------- dedup attention over 800 unique keys (padded to 832) ----------------
// key row r: r<784 -> token r (weight = multiplicity of its window)
//            784<=r<800 -> mean r-784 (weight 16); r>=800 -> pad (weight 0)
// grid (7, NHEAD, BS*NCH2), block 128. Scores tiny -> softmax without max pass.
// No weight branch: zero-weight keys contribute exactly 0 (keeps cross-key ILP).
__global__ __launch_bounds__(128) void k_attn(const float* __restrict__ qb,
                                              const float* __restrict__ kb,
                                              const float* __restrict__ vb,
                                              const float* __restrict__ km,
                                              const float* __restrict__ vm,
                                              const float* __restrict__ cnt,
                                              float* __restrict__ pl,
                                              float* __restrict__ pacc) {
    int qt0   = blockIdx.x * 128;
    int h     = blockIdx.y;
    int b     = blockIdx.z / NCH2;
    int chunk = blockIdx.z % NCH2;
    int t = threadIdx.x;
    int l = qt0 + t;
    int lq = (l < NTOK) ? l : 0;
    int w = lq / WS, p = lq % WS;
    int n = ((w / MW) * WWIN + p / WWIN) * HH + (w % MW) * WWIN + (p % WWIN);

    const ulonglong2* qrow = (const ulonglong2*)(qb + ((size_t)(b * NTOK + n) * DMODEL + h * DH));
    ull qp[16];
    #pragma unroll
    for (int i = 0; i < 8; i++) {
        ulonglong2 qq = qrow[i];
        qp[2 * i + 0] = qq.x;
        qp[2 * i + 1] = qq.y;
    }

    __shared__ __align__(16) float4 Ks[KT][DH / 4];
    __shared__ __align__(16) float4 Vs[KT][DH / 4];
    __shared__ float  wgt[KT];
    __shared__ float  scnt[NW];
    if (t < NW) scnt[t] = cnt[b * NW + t];

    float lsum = 0.f;
    ull acc[16];
    #pragma unroll
    for (int d = 0; d < 16; d++) acc[d] = 0ull;
    const float scale = 0.17677669529663687f;   // 32^-0.5

    int s0 = chunk * CH2;
    for (int tile = 0; tile < CH2 / KT; tile++) {
        int sbase = s0 + tile * KT;
        __syncthreads();
        // load 2*KT rows x 8 float4 = 256 float4, 128 threads -> 2 each
        #pragma unroll
        for (int i = 0; i < 2; i++) {
            int f = i * 128 + t;
            int r = f >> 3, c4 = f & 7;
            int rr = (r < KT) ? r : r - KT;
            int gr = sbase + rr;
            const float4* src;
            int rowbase;
            if (gr < NTOK) {
                src = (r < KT) ? (const float4*)kb : (const float4*)vb;
                rowbase = b * NTOK + gr;
            } else {
                int mi = gr - NTOK;
                if (mi >= NW) mi = 0;            // pad rows: weight 0, data harmless
                src = (r < KT) ? (const float4*)km : (const float4*)vm;
                rowbase = b * NW + mi;
            }
            float4 val = src[rowbase * (DMODEL / 4) + h * (DH / 4) + c4];
            if (r < KT) Ks[r][c4] = val; else Vs[r - KT][c4] = val;
        }
        if (t < KT) {
            int gr = sbase + t;
            float wv;
            if (gr < NTOK) {
                int win = (gr / (WWIN * HH)) * MW + (gr % HH) / WWIN;
                wv = scnt[win];
            } else wv = (gr < NTOK + NW) ? 16.f : 0.f;
            wgt[t] = wv;
        }
        __syncthreads();
        #pragma unroll 8
        for (int kk = 0; kk < KT; kk++) {
            const ulonglong2* krow = (const ulonglong2*)&Ks[kk][0];
            // 4 independent packed score chains (depth 4 instead of 16)
            ull sa = 0ull, sb = 0ull, sc = 0ull, sd = 0ull;
            #pragma unroll
            for (int c = 0; c < 2; c++) {
                ulonglong2 kv0 = krow[4 * c + 0];
                ulonglong2 kv1 = krow[4 * c + 1];
                ulonglong2 kv2 = krow[4 * c + 2];
                ulonglong2 kv3 = krow[4 * c + 3];
                ffma2(sa, qp[8 * c + 0], kv0.x); ffma2(sb, qp[8 * c + 1], kv0.y);
                ffma2(sc, qp[8 * c + 2], kv1.x); ffma2(sd, qp[8 * c + 3], kv1.y);
                ffma2(sa, qp[8 * c + 4], kv2.x); ffma2(sb, qp[8 * c + 5], kv2.y);
                ffma2(sc, qp[8 * c + 6], kv3.x); ffma2(sd, qp[8 * c + 7], kv3.y);
            }
            add2(sa, sb); add2(sc, sd); add2(sa, sc);
            float slo, shi;
            unpack2(sa, slo, shi);
            float pe = wgt[kk] * __expf((slo + shi) * scale);
            lsum += pe;
            ull pp = pack2(pe, pe);
            const ulonglong2* vrow = (const ulonglong2*)&Vs[kk][0];
            #pragma unroll
            for (int c = 0; c < 8; c++) {
                ulonglong2 vv = vrow[c];
                ffma2(acc[2 * c + 0], pp, vv.x);
                ffma2(acc[2 * c + 1], pp, vv.y);
            }
        }
    }
    if (l < NTOK) {
        int pbase = ((b * NHEAD + h) * NCH2 + chunk) * NTOK + l;
        pl[pbase] = lsum;
        #pragma unroll
        for (int d = 0; d < 16; d++) {
            float f0, f1;
            unpack2(acc[d], f0, f1);
            pacc[(size_t)pbase * DH + 2 * d + 0] = f0;
            pacc[(size_t)pbase * DH + 2 * d + 1] = f1;
        }
    }
}

// ---------------- combine split-K partials -> msg ----------------
__global__ void k_combine(const float* __restrict__ pl, const float* __restrict__ pacc,
                          float* __restrict__ msg) {
    int gq   = blockIdx.x * 8 + (threadIdx.x >> 5);   // BS*NHEAD*NTOK units
    int lane = threadIdx.x & 31;
    int b = gq / (NHEAD * NTOK);
    int rem = gq % (NHEAD * NTOK);
    int h = rem / NTOK, l = rem % NTOK;
    float Ls = 0.f, o = 0.f;
    #pragma unroll
    for (int c = 0; c < NCH2; c++) {
        int pbase = ((b * NHEAD + h) * NCH2 + c) * NTOK + l;
        Ls += pl[pbase];
        o  += pacc[(size_t)pbase * DH + lane];
    }
    msg[(b * NTOK + l) * DMODEL + h * DH + lane] = o / Ls;
}

// ---------------- LN1 + concat: message = [xf | LN(msg2)] ----------------
__global__ void k_ln1(const float* __restrict__ msg2, const float* __restrict__ xf,
                      const float* __restrict__ g, const float* __restrict__ bta,
                      float* __restrict__ message) {
    int row = blockIdx.x;       // 0..BS*NTOK-1
    int c = threadIdx.x;        // 256
    __shared__ float red[DMODEL];
    float v = msg2[row * DMODEL + c];
    red[c] = v; __syncthreads();
    for (int s = 128; s > 0; s >>= 1) { if (c < s) red[c] += red[c + s]; __syncthreads(); }
    float mu = red[0] * (1.f / DMODEL);
    __syncthreads();
    float dv = v - mu;
    red[c] = dv * dv; __syncthreads();
    for (int s = 128; s > 0; s >>= 1) { if (c < s) red[c] += red[c + s]; __syncthreads(); }
    float var = red[0] * (1.f / DMODEL);
    float outv = dv * rsqrtf(var + 1e-5f) * g[c] + bta[c];
    message[row * DFF + DMODEL + c] = outv;
    message[row * DFF + c] = xf[row * DMODEL + c];
}

// ---------------- depthwise 3x3 conv + bias + exact gelu ----------------
__global__ void k_dwconv(const float* __restrict__ y1, const float* __restrict__ dww,
                         const float* __restrict__ dwb, float* __restrict__ y2) {
    int b = blockIdx.y;
    int nn = blockIdx.x;        // 0..783
    int c = threadIdx.x;        // 512
    int r = nn / HH, col = nn % HH;
    float s = 0.f;
    #pragma unroll
    for (int dr = -1; dr <= 1; dr++)
        #pragma unroll
        for (int dc = -1; dc <= 1; dc++) {
            int rr = r + dr, cc = col + dc;
            if (rr >= 0 && rr < HH && cc >= 0 && cc < HH)
                s += y1[(b * NTOK + rr * HH + cc) * DFF + c] * dww[c * 9 + (dr + 1) * 3 + (dc + 1)];
        }
    s += dwb[c];
    float gl = 0.5f * s * (1.f + erff(s * 0.70710678118654752f));
    y2[(b * NTOK + nn) * DFF + c] = gl;
}

// ---------------- LN2 + residual + coalesced transposed store ----------------
// grid (25, 2), block 256 (8 warps x 4 rows = 32 tokens per block)
__global__ __launch_bounds__(256) void k_ln2(const float* __restrict__ z, const float* __restrict__ xf,
                                             const float* __restrict__ g, const float* __restrict__ bta,
                                             float* __restrict__ out) {
    __shared__ float tile[DMODEL][33];
    int b = blockIdx.y, n0 = blockIdx.x * 32;
    int rows = NTOK - n0; if (rows > 32) rows = 32;
    int wid = threadIdx.x >> 5, lane = threadIdx.x & 31;

    #pragma unroll
    for (int i = 0; i < 4; i++) {
        int rl = wid * 4 + i;
        if (rl >= rows) break;
        int row = b * NTOK + n0 + rl;
        float vals[8];
        float s = 0.f;
        #pragma unroll
        for (int j = 0; j < 8; j++) {
            vals[j] = z[(size_t)row * DMODEL + lane + j * 32];
            s += vals[j];
        }
        #pragma unroll
        for (int o = 16; o > 0; o >>= 1) s += __shfl_xor_sync(0xffffffff, s, o);
        float mu = s * (1.f / DMODEL);
        float sq = 0.f;
        #pragma unroll
        for (int j = 0; j < 8; j++) { float d = vals[j] - mu; sq += d * d; }
        #pragma unroll
        for (int o = 16; o > 0; o >>= 1) sq += __shfl_xor_sync(0xffffffff, sq, o);
        float rs = rsqrtf(sq * (1.f / DMODEL) + 1e-5f);
        #pragma unroll
        for (int j = 0; j < 8; j++) {
            int c = lane + j * 32;
            float o2 = (vals[j] - mu) * rs * g[c] + bta[c] + xf[(size_t)row * DMODEL + c];
            tile[c][rl] = o2;
        }
    }
    __syncthreads();
    // coalesced store: warp w covers c = w*32..w*32+31; lane = token within tile
    if (lane < rows) {
        #pragma unroll
        for (int i = 0; i < 32; i++) {
            int c = wid * 32 + i;
            out[((size_t)b * DMODEL + c) * NTOK + n0 + lane] = tile[c][lane];
        }
    }
}

// ---------------- host launcher ----------------
static float* symf(const void* s) { void* p = nullptr; cudaGetSymbolAddress(&p, s); return (float*)p; }

extern "C" void kernel_launch(void* const* d_in, const int* in_sizes, int n_in,
                              void* d_out, int out_size) {
    const float* x    = (const float*)d_in[0];
    const float* Wq   = (const float*)d_in[1];
    const float* Wk   = (const float*)d_in[2];
    const float* Wv   = (const float*)d_in[3];
    const float* Wm   = (const float*)d_in[4];
    const float* ln1g = (const float*)d_in[5];
    const float* ln1b = (const float*)d_in[6];
    const float* fc1w = (const float*)d_in[7];
    const float* fc1b = (const float*)d_in[8];
    const float* dww  = (const float*)d_in[9];
    const float* dwb  = (const float*)d_in[10];
    const float* fc2w = (const float*)d_in[11];
    const float* fc2b = (const float*)d_in[12];
    const float* ln2g = (const float*)d_in[13];
    const float* ln2b = (const float*)d_in[14];
    float* out = (float*)d_out;

    float* xf   = symf(g_xf);
    float* q    = symf(g_q);
    float* k    = symf(g_k);
    float* v    = symf(g_v);
    float* qm   = symf(g_qm);
    float* km   = symf(g_km);
    float* vm   = symf(g_vm);
    float* cnt  = symf(g_cnt);
    float* pl   = symf(g_pl);
    float* pacc = symf(g_pacc);
    float* msg  = symf(g_msg);
    float* msg2 = symf(g_msg2);
    float* mesg = symf(g_mesg);
    float* y1   = symf(g_y1);
    float* y2   = symf(g_y2);
    float* z    = symf(g_z);

    const int M = BS * NTOK;   // 1568

    k_transpose<<<dim3(25, 8, BS), dim3(32, 8)>>>(x, xf);

    k_qkv<<<dim3(12, 25), 128>>>(xf, Wq, Wk, Wv, q, k, v);

    k_means<<<BS * NW, DMODEL>>>(q, k, v, qm, km, vm);
    k_topk<<<BS, 256>>>(qm, km, cnt);

    k_attn<<<dim3(7, NHEAD, BS * NCH2), 128>>>(q, k, v, km, vm, cnt, pl, pacc);
    k_combine<<<(BS * NHEAD * NTOK) / 8, 256>>>(pl, pacc, msg);

    k_gemm3<<<dim3(4, 25), 128>>>(msg, Wm, nullptr, msg2, M, DMODEL, DMODEL, 0);
    k_ln1<<<M, DMODEL>>>(msg2, xf, ln1g, ln1b, mesg);

    k_gemm3<<<dim3(8, 25), 128>>>(mesg, fc1w, fc1b, y1, M, DFF, DFF, 1);
    k_dwconv<<<dim3(NTOK, BS), DFF>>>(y1, dww, dwb, y2);
    k_gemm3<<<dim3(4, 25), 128>>>(y2, fc2w, fc2b, z, M, DMODEL, DFF, 0);

    k_ln2<<<dim3(25, BS), 256>>>(z, xf, ln2g, ln2b, out);
}

// round 11
// speedup vs baseline: 1.2730x; 1.0375x over previous
#include <cuda_runtime.h>
#include <math.h>

// ---------------- problem constants ----------------
#define BS      2
#define DMODEL  256
#define HH      28
#define NTOK    784          // 28*28
#define WWIN    7
#define MW      4            // windows per side
#define NW      16
#define WS      49
#define KTOP    8
#define NHEAD   8
#define DH      32
#define DFF     512

// dedup attention: 784 token keys + 16 mean keys = 800, padded to 832
#define NCH2    4
#define CH2     208          // keys per chunk
#define KT      16           // key tile

typedef unsigned long long ull;

// ---------------- f32x2 packed math helpers ----------------
__device__ __forceinline__ ull pack2(float a, float b) {
    ull r;
    asm("mov.b64 %0, {%1, %2};" : "=l"(r) : "f"(a), "f"(b));
    return r;
}
__device__ __forceinline__ void unpack2(ull p, float& a, float& b) {
    asm("mov.b64 {%0, %1}, %2;" : "=f"(a), "=f"(b) : "l"(p));
}
__device__ __forceinline__ void ffma2(ull& d, ull a, ull b) {
    asm("fma.rn.f32x2 %0, %1, %2, %0;" : "+l"(d) : "l"(a), "l"(b));
}
__device__ __forceinline__ void add2(ull& d, ull a) {
    asm("add.rn.f32x2 %0, %0, %1;" : "+l"(d) : "l"(a));
}

// ---------------- scratch (device globals; no allocs allowed) ----------------
__device__ float g_xf  [BS*NTOK*DMODEL];
__device__ float g_q   [BS*NTOK*DMODEL];
__device__ float g_k   [BS*NTOK*DMODEL];
__device__ float g_v   [BS*NTOK*DMODEL];
__device__ float g_qm  [BS*NW*DMODEL];
__device__ float g_km  [BS*NW*DMODEL];
__device__ float g_vm  [BS*NW*DMODEL];
__device__ int   g_icnt[BS*NW];
__device__ float g_pl  [BS*NHEAD*NCH2*NTOK];
__device__ float g_pacc[BS*NHEAD*NCH2*NTOK*DH];
__device__ float g_msg [BS*NTOK*DMODEL];
__device__ float g_msg2[BS*NTOK*DMODEL];
__device__ float g_mesg[BS*NTOK*DFF];
__device__ float g_y1  [BS*NTOK*DFF];
__device__ float g_y2  [BS*NTOK*DFF];
__device__ float g_z   [BS*NTOK*DMODEL];

// ---------------- x (b,d,hw) -> xf (b,hw,d) ----------------
__global__ void k_transpose(const float* __restrict__ x, float* __restrict__ xf) {
    __shared__ float tile[32][33];
    int b  = blockIdx.z;
    int c0 = blockIdx.y * 32, n0 = blockIdx.x * 32;
    int tx = threadIdx.x, ty = threadIdx.y;   // (32, 8)
    #pragma unroll
    for (int i = 0; i < 32; i += 8) {
        int c = c0 + ty + i, n = n0 + tx;
        if (c < DMODEL && n < NTOK) tile[ty + i][tx] = x[(b * DMODEL + c) * NTOK + n];
    }
    __syncthreads();
    #pragma unroll
    for (int i = 0; i < 32; i += 8) {
        int n = n0 + ty + i, c = c0 + tx;
        if (n < NTOK && c < DMODEL) xf[(b * NTOK + n) * DMODEL + c] = tile[tx][ty + i];
    }
}

// ---------------- packed-FMA GEMM: C[M,N] = act(A[M,K] @ B[N,K]^T + bias) ----------------
// 64x64 tile, 256 threads (8 warps -> 2+ warps/SMSP). Each thread: 4 rows x 4 cols
// as 8 packed f32x2 accumulators. Requires N % 64 == 0, K % 16 == 0.
__device__ __forceinline__ void gemm5_body(const float* __restrict__ A, const float* __restrict__ B,
                                           const float* __restrict__ bias, float* __restrict__ C,
                                           int M, int N, int K, int act, int by, int bx) {
    __shared__ __align__(16) float As[16][68];
    __shared__ __align__(16) float Bs[16][68];
    int bm = by * 64, bn = bx * 64;
    int tid = threadIdx.x;          // 0..255
    int tr = tid >> 4;              // 0..15
    int tc = tid & 15;              // 0..15

    ull acc[4][2];
    #pragma unroll
    for (int i = 0; i < 4; i++) { acc[i][0] = 0ull; acc[i][1] = 0ull; }

    int lr = tid >> 2, lk4 = tid & 3;    // loader: row 0..63, k-quad 0..3
    for (int k0 = 0; k0 < K; k0 += 16) {
        {
            int ga = bm + lr;
            float4 av = (ga < M) ? *(const float4*)&A[(size_t)ga * K + k0 + lk4 * 4]
                                 : make_float4(0.f, 0.f, 0.f, 0.f);
            As[lk4 * 4 + 0][lr] = av.x;
            As[lk4 * 4 + 1][lr] = av.y;
            As[lk4 * 4 + 2][lr] = av.z;
            As[lk4 * 4 + 3][lr] = av.w;
            int gb = bn + lr;
            float4 bv = (gb < N) ? *(const float4*)&B[(size_t)gb * K + k0 + lk4 * 4]
                                 : make_float4(0.f, 0.f, 0.f, 0.f);
            Bs[lk4 * 4 + 0][lr] = bv.x;
            Bs[lk4 * 4 + 1][lr] = bv.y;
            Bs[lk4 * 4 + 2][lr] = bv.z;
            Bs[lk4 * 4 + 3][lr] = bv.w;
        }
        __syncthreads();
        #pragma unroll
        for (int kq = 0; kq < 16; kq++) {
            float4 a4 = *(const float4*)&As[kq][tr * 4];
            ulonglong2 bb = *(const ulonglong2*)&Bs[kq][tc * 4];
            ull pa0 = pack2(a4.x, a4.x);
            ull pa1 = pack2(a4.y, a4.y);
            ull pa2 = pack2(a4.z, a4.z);
            ull pa3 = pack2(a4.w, a4.w);
            ffma2(acc[0][0], pa0, bb.x); ffma2(acc[0][1], pa0, bb.y);
            ffma2(acc[1][0], pa1, bb.x); ffma2(acc[1][1], pa1, bb.y);
            ffma2(acc[2][0], pa2, bb.x); ffma2(acc[2][1], pa2, bb.y);
            ffma2(acc[3][0], pa3, bb.x); ffma2(acc[3][1], pa3, bb.y);
        }
        __syncthreads();
    }

    int c0 = bn + tc * 4;
    #pragma unroll
    for (int i = 0; i < 4; i++) {
        int r = bm + tr * 4 + i;
        if (r >= M) continue;
        float4 o;
        unpack2(acc[i][0], o.x, o.y);
        unpack2(acc[i][1], o.z, o.w);
        if (bias) {
            o.x += bias[c0 + 0]; o.y += bias[c0 + 1];
            o.z += bias[c0 + 2]; o.w += bias[c0 + 3];
        }
        if (act == 1) {
            o.x = fmaxf(o.x, 0.f); o.y = fmaxf(o.y, 0.f);
            o.z = fmaxf(o.z, 0.f); o.w = fmaxf(o.w, 0.f);
        }
        *(float4*)&C[(size_t)r * N + c0] = o;
    }
}

__global__ __launch_bounds__(256) void k_gemm5(const float* __restrict__ A, const float* __restrict__ B,
                                               const float* __restrict__ bias, float* __restrict__ C,
                                               int M, int N, int K, int act) {
    gemm5_body(A, B, bias, C, M, N, K, act, blockIdx.y, blockIdx.x);
}

// fused QKV: grid.x = 12 (3 weights x 4 col tiles), grid.y = 25
__global__ __launch_bounds__(256) void k_qkv(const float* __restrict__ A,
                                             const float* __restrict__ Wq, const float* __restrict__ Wk,
                                             const float* __restrict__ Wv,
                                             float* __restrict__ q, float* __restrict__ k, float* __restrict__ v) {
    int sel = blockIdx.x >> 2;
    const float* B = (sel == 0) ? Wq : (sel == 1) ? Wk : Wv;
    float* C = (sel == 0) ? q : (sel == 1) ? k : v;
    gemm5_body(A, B, nullptr, C, BS * NTOK, DMODEL, DMODEL, 0, blockIdx.y, blockIdx.x & 3);
}

// ---------------- per-window means of q,k,v (+ zero topk counters) ----------------
__global__ void k_means(const float* __restrict__ q, const float* __restrict__ k,
                        const float* __restrict__ v,
                        float* __restrict__ qm, float* __restrict__ km, float* __restrict__ vm,
                        int* __restrict__ icnt) {
    int b = blockIdx.x / NW, w = blockIdx.x % NW;
    int c = threadIdx.x;
    if (w == 0 && c < NW) icnt[b * NW + c] = 0;
    int wr = w / MW, wc = w % MW;
    float sq = 0.f, sk = 0.f, sv = 0.f;
    for (int p = 0; p < WS; p++) {
        int pr = p / WWIN, pc = p % WWIN;
        int n  = (wr * WWIN + pr) * HH + wc * WWIN + pc;
        int o  = (b * NTOK + n) * DMODEL + c;
        sq += q[o]; sk += k[o]; sv += v[o];
    }
    int o = (b * NW + w) * DMODEL + c;
    qm[o] = sq * (1.f / 49.f);
    km[o] = sk * (1.f / 49.f);
    vm[o] = sv * (1.f / 49.f);
}

// ---------------- topk: one block per query window row ----------------
// grid (NW, BS), 256 threads. Parallel 16 dots, serial top-8 over 16 values.
__global__ __launch_bounds__(256) void k_topk(const float* __restrict__ qm, const float* __restrict__ km,
                                              int* __restrict__ icnt) {
    int i = blockIdx.x, b = blockIdx.y;
    __shared__ __align__(16) float4 q4s[64];
    __shared__ float red[NW][17];
    __shared__ float simr[NW];
    int t = threadIdx.x;
    if (t < 64) q4s[t] = ((const float4*)qm)[(b * NW + i) * 64 + t];
    __syncthreads();
    int j = t >> 4, part = t & 15;
    const float4* krow = (const float4*)km + (b * NW + j) * 64;
    float s = 0.f;
    #pragma unroll
    for (int u = 0; u < 4; u++) {
        float4 kk = krow[part * 4 + u];
        float4 qq = q4s[part * 4 + u];
        s += qq.x * kk.x + qq.y * kk.y + qq.z * kk.z + qq.w * kk.w;
    }
    red[j][part] = s;
    __syncthreads();
    if (part == 0) {
        float tot = 0.f;
        #pragma unroll
        for (int u = 0; u < 16; u++) tot += red[j][u];
        simr[j] = tot;
    }
    __syncthreads();
    if (t == 0) {
        float row[NW];
        #pragma unroll
        for (int u = 0; u < NW; u++) row[u] = simr[u];
        #pragma unroll
        for (int r = 0; r < KTOP; r++) {
            int best = 0; float bv = -1e30f;
            #pragma unroll
            for (int u = 0; u < NW; u++)
                if (row[u] > bv) { bv = row[u]; best = u; }
            row[best] = -2e30f;
            atomicAdd(&icnt[b * NW + best], 1);
        }
    }
}

// ---------------- dedup attention over 800 unique keys (padded to 832) ----------------
// key row r: r<784 -> token r (weight = multiplicity of its window)
//            784<=r<800 -> mean r-784 (weight 16); r>=800 -> pad (weight 0)
// grid (7, NHEAD, BS*NCH2), block 128. Scores tiny -> softmax without max pass.
// No weight branch: zero-weight keys contribute exactly 0 (keeps cross-key ILP).
__global__ __launch_bounds__(128) void k_attn(const float* __restrict__ qb,
                                              const float* __restrict__ kb,
                                              const float* __restrict__ vb,
                                              const float* __restrict__ km,
                                              const float* __restrict__ vm,
                                              const int* __restrict__ icnt,
                                              float* __restrict__ pl,
                                              float* __restrict__ pacc) {
    int qt0   = blockIdx.x * 128;
    int h     = blockIdx.y;
    int b     = blockIdx.z / NCH2;
    int chunk = blockIdx.z % NCH2;
    int t = threadIdx.x;
    int l = qt0 + t;
    int lq = (l < NTOK) ? l : 0;
    int w = lq / WS, p = lq % WS;
    int n = ((w / MW) * WWIN + p / WWIN) * HH + (w % MW) * WWIN + (p % WWIN);

    const ulonglong2* qrow = (const ulonglong2*)(qb + ((size_t)(b * NTOK + n) * DMODEL + h * DH));
    ull qp[16];
    #pragma unroll
    for (int i = 0; i < 8; i++) {
        ulonglong2 qq = qrow[i];
        qp[2 * i + 0] = qq.x;
        qp[2 * i + 1] = qq.y;
    }

    __shared__ __align__(16) float4 Ks[KT][DH / 4];
    __shared__ __align__(16) float4 Vs[KT][DH / 4];
    __shared__ float  wgt[KT];
    __shared__ float  scnt[NW];
    if (t < NW) scnt[t] = (float)icnt[b * NW + t];

    float lsum = 0.f;
    ull acc[16];
    #pragma unroll
    for (int d = 0; d < 16; d++) acc[d] = 0ull;
    const float scale = 0.17677669529663687f;   // 32^-0.5

    int s0 = chunk * CH2;
    for (int tile = 0; tile < CH2 / KT; tile++) {
        int sbase = s0 + tile * KT;
        __syncthreads();
        // load 2*KT rows x 8 float4 = 256 float4, 128 threads -> 2 each
        #pragma unroll
        for (int i = 0; i < 2; i++) {
            int f = i * 128 + t;
            int r = f >> 3, c4 = f & 7;
            int rr = (r < KT) ? r : r - KT;
            int gr = sbase + rr;
            const float4* src;
            int rowbase;
            if (gr < NTOK) {
                src = (r < KT) ? (const float4*)kb : (const float4*)vb;
                rowbase = b * NTOK + gr;
            } else {
                int mi = gr - NTOK;
                if (mi >= NW) mi = 0;            // pad rows: weight 0, data harmless
                src = (r < KT) ? (const float4*)km : (const float4*)vm;
                rowbase = b * NW + mi;
            }
            float4 val = src[rowbase * (DMODEL / 4) + h * (DH / 4) + c4];
            if (r < KT) Ks[r][c4] = val; else Vs[r - KT][c4] = val;
        }
        if (t < KT) {
            int gr = sbase + t;
            float wv;
            if (gr < NTOK) {
                int win = (gr / (WWIN * HH)) * MW + (gr % HH) / WWIN;
                wv = scnt[win];
            } else wv = (gr < NTOK + NW) ? 16.f : 0.f;
            wgt[t] = wv;
        }
        __syncthreads();
        #pragma unroll 8
        for (int kk = 0; kk < KT; kk++) {
            const ulonglong2* krow = (const ulonglong2*)&Ks[kk][0];
            // 4 independent packed score chains (depth 4 instead of 16)
            ull sa = 0ull, sb = 0ull, sc = 0ull, sd = 0ull;
            #pragma unroll
            for (int c = 0; c < 2; c++) {
                ulonglong2 kv0 = krow[4 * c + 0];
                ulonglong2 kv1 = krow[4 * c + 1];
                ulonglong2 kv2 = krow[4 * c + 2];
                ulonglong2 kv3 = krow[4 * c + 3];
                ffma2(sa, qp[8 * c + 0], kv0.x); ffma2(sb, qp[8 * c + 1], kv0.y);
                ffma2(sc, qp[8 * c + 2], kv1.x); ffma2(sd, qp[8 * c + 3], kv1.y);
                ffma2(sa, qp[8 * c + 4], kv2.x); ffma2(sb, qp[8 * c + 5], kv2.y);
                ffma2(sc, qp[8 * c + 6], kv3.x); ffma2(sd, qp[8 * c + 7], kv3.y);
            }
            add2(sa, sb); add2(sc, sd); add2(sa, sc);
            float slo, shi;
            unpack2(sa, slo, shi);
            float pe = wgt[kk] * __expf((slo + shi) * scale);
            lsum += pe;
            ull pp = pack2(pe, pe);
            const ulonglong2* vrow = (const ulonglong2*)&Vs[kk][0];
            #pragma unroll
            for (int c = 0; c < 8; c++) {
                ulonglong2 vv = vrow[c];
                ffma2(acc[2 * c + 0], pp, vv.x);
                ffma2(acc[2 * c + 1], pp, vv.y);
            }
        }
    }
    if (l < NTOK) {
        int pbase = ((b * NHEAD + h) * NCH2 + chunk) * NTOK + l;
        pl[pbase] = lsum;
        #pragma unroll
        for (int d = 0; d < 16; d++) {
            float f0, f1;
            unpack2(acc[d], f0, f1);
            pacc[(size_t)pbase * DH + 2 * d + 0] = f0;
            pacc[(size_t)pbase * DH + 2 * d + 1] = f1;
        }
    }
}

// ---------------- combine split-K partials -> msg ----------------
__global__ void k_combine(const float* __restrict__ pl, const float* __restrict__ pacc,
                          float* __restrict__ msg) {
    int gq   = blockIdx.x * 8 + (threadIdx.x >> 5);   // BS*NHEAD*NTOK units
    int lane = threadIdx.x & 31;
    int b = gq / (NHEAD * NTOK);
    int rem = gq % (NHEAD * NTOK);
    int h = rem / NTOK, l = rem % NTOK;
    float Ls = 0.f, o = 0.f;
    #pragma unroll
    for (int c = 0; c < NCH2; c++) {
        int pbase = ((b * NHEAD + h) * NCH2 + c) * NTOK + l;
        Ls += pl[pbase];
        o  += pacc[(size_t)pbase * DH + lane];
    }
    msg[(b * NTOK + l) * DMODEL + h * DH + lane] = o / Ls;
}

// ---------------- LN1 + concat: message = [xf | LN(msg2)] ----------------
__global__ void k_ln1(const float* __restrict__ msg2, const float* __restrict__ xf,
                      const float* __restrict__ g, const float* __restrict__ bta,
                      float* __restrict__ message) {
    int row = blockIdx.x;       // 0..BS*NTOK-1
    int c = threadIdx.x;        // 256
    __shared__ float red[DMODEL];
    float v = msg2[row * DMODEL + c];
    red[c] = v; __syncthreads();
    for (int s = 128; s > 0; s >>= 1) { if (c < s) red[c] += red[c + s]; __syncthreads(); }
    float mu = red[0] * (1.f / DMODEL);
    __syncthreads();
    float dv = v - mu;
    red[c] = dv * dv; __syncthreads();
    for (int s = 128; s > 0; s >>= 1) { if (c < s) red[c] += red[c + s]; __syncthreads(); }
    float var = red[0] * (1.f / DMODEL);
    float outv = dv * rsqrtf(var + 1e-5f) * g[c] + bta[c];
    message[row * DFF + DMODEL + c] = outv;
    message[row * DFF + c] = xf[row * DMODEL + c];
}

// ---------------- depthwise 3x3 conv + bias + exact gelu ----------------
__global__ void k_dwconv(const float* __restrict__ y1, const float* __restrict__ dww,
                         const float* __restrict__ dwb, float* __restrict__ y2) {
    int b = blockIdx.y;
    int nn = blockIdx.x;        // 0..783
    int c = threadIdx.x;        // 512
    int r = nn / HH, col = nn % HH;
    float s = 0.f;
    #pragma unroll
    for (int dr = -1; dr <= 1; dr++)
        #pragma unroll
        for (int dc = -1; dc <= 1; dc++) {
            int rr = r + dr, cc = col + dc;
            if (rr >= 0 && rr < HH && cc >= 0 && cc < HH)
                s += y1[(b * NTOK + rr * HH + cc) * DFF + c] * dww[c * 9 + (dr + 1) * 3 + (dc + 1)];
        }
    s += dwb[c];
    float gl = 0.5f * s * (1.f + erff(s * 0.70710678118654752f));
    y2[(b * NTOK + nn) * DFF + c] = gl;
}

// ---------------- LN2 + residual + coalesced transposed store ----------------
// grid (25, 2), block 256 (8 warps x 4 rows = 32 tokens per block)
__global__ __launch_bounds__(256) void k_ln2(const float* __restrict__ z, const float* __restrict__ xf,
                                             const float* __restrict__ g, const float* __restrict__ bta,
                                             float* __restrict__ out) {
    __shared__ float tile[DMODEL][33];
    int b = blockIdx.y, n0 = blockIdx.x * 32;
    int rows = NTOK - n0; if (rows > 32) rows = 32;
    int wid = threadIdx.x >> 5, lane = threadIdx.x & 31;

    #pragma unroll
    for (int i = 0; i < 4; i++) {
        int rl = wid * 4 + i;
        if (rl >= rows) break;
        int row = b * NTOK + n0 + rl;
        float vals[8];
        float s = 0.f;
        #pragma unroll
        for (int j = 0; j < 8; j++) {
            vals[j] = z[(size_t)row * DMODEL + lane + j * 32];
            s += vals[j];
        }
        #pragma unroll
        for (int o = 16; o > 0; o >>= 1) s += __shfl_xor_sync(0xffffffff, s, o);
        float mu = s * (1.f / DMODEL);
        float sq = 0.f;
        #pragma unroll
        for (int j = 0; j < 8; j++) { float d = vals[j] - mu; sq += d * d; }
        #pragma unroll
        for (int o = 16; o > 0; o >>= 1) sq += __shfl_xor_sync(0xffffffff, sq, o);
        float rs = rsqrtf(sq * (1.f / DMODEL) + 1e-5f);
        #pragma unroll
        for (int j = 0; j < 8; j++) {
            int c = lane + j * 32;
            float o2 = (vals[j] - mu) * rs * g[c] + bta[c] + xf[(size_t)row * DMODEL + c];
            tile[c][rl] = o2;
        }
    }
    __syncthreads();
    // coalesced store: warp w covers c = w*32..w*32+31; lane = token within tile
    if (lane < rows) {
        #pragma unroll
        for (int i = 0; i < 32; i++) {
            int c = wid * 32 + i;
            out[((size_t)b * DMODEL + c) * NTOK + n0 + lane] = tile[c][lane];
        }
    }
}

// ---------------- host launcher ----------------
static float* symf(const void* s) { void* p = nullptr; cudaGetSymbolAddress(&p, s); return (float*)p; }

extern "C" void kernel_launch(void* const* d_in, const int* in_sizes, int n_in,
                              void* d_out, int out_size) {
    const float* x    = (const float*)d_in[0];
    const float* Wq   = (const float*)d_in[1];
    const float* Wk   = (const float*)d_in[2];
    const float* Wv   = (const float*)d_in[3];
    const float* Wm   = (const float*)d_in[4];
    const float* ln1g = (const float*)d_in[5];
    const float* ln1b = (const float*)d_in[6];
    const float* fc1w = (const float*)d_in[7];
    const float* fc1b = (const float*)d_in[8];
    const float* dww  = (const float*)d_in[9];
    const float* dwb  = (const float*)d_in[10];
    const float* fc2w = (const float*)d_in[11];
    const float* fc2b = (const float*)d_in[12];
    const float* ln2g = (const float*)d_in[13];
    const float* ln2b = (const float*)d_in[14];
    float* out = (float*)d_out;

    float* xf   = symf(g_xf);
    float* q    = symf(g_q);
    float* k    = symf(g_k);
    float* v    = symf(g_v);
    float* qm   = symf(g_qm);
    float* km   = symf(g_km);
    float* vm   = symf(g_vm);
    int*   icnt = (int*)symf(g_icnt);
    float* pl   = symf(g_pl);
    float* pacc = symf(g_pacc);
    float* msg  = symf(g_msg);
    float* msg2 = symf(g_msg2);
    float* mesg = symf(g_mesg);
    float* y1   = symf(g_y1);
    float* y2   = symf(g_y2);
    float* z    = symf(g_z);

    const int M = BS * NTOK;   // 1568

    k_transpose<<<dim3(25, 8, BS), dim3(32, 8)>>>(x, xf);

    k_qkv<<<dim3(12, 25), 256>>>(xf, Wq, Wk, Wv, q, k, v);

    k_means<<<BS * NW, DMODEL>>>(q, k, v, qm, km, vm, icnt);
    k_topk<<<dim3(NW, BS), 256>>>(qm, km, icnt);

    k_attn<<<dim3(7, NHEAD, BS * NCH2), 128>>>(q, k, v, km, vm, icnt, pl, pacc);
    k_combine<<<(BS * NHEAD * NTOK) / 8, 256>>>(pl, pacc, msg);

    k_gemm5<<<dim3(4, 25), 256>>>(msg, Wm, nullptr, msg2, M, DMODEL, DMODEL, 0);
    k_ln1<<<M, DMODEL>>>(msg2, xf, ln1g, ln1b, mesg);

    k_gemm5<<<dim3(8, 25), 256>>>(mesg, fc1w, fc1b, y1, M, DFF, DFF, 1);
    k_dwconv<<<dim3(NTOK, BS), DFF>>>(y1, dww, dwb, y2);
    k_gemm5<<<dim3(4, 25), 256>>>(y2, fc2w, fc2b, z, M, DMODEL, DFF, 0);

    k_ln2<<<dim3(25, BS), 256>>>(z, xf, ln2g, ln2b, out);
}